// round 2
// baseline (speedup 1.0000x reference)
#include <cuda_runtime.h>

#define T_STEPS 2048
#define BATCH   512
#define NH      32
#define NC      5
#define T_PAD   (T_STEPS + 8)
#define ROW_F   (BATCH * NH)   // floats per time step = 16384

typedef unsigned long long u64;

// scratch: U[t][b][j], padded by 8 steps so the prefetch pipe never clamps
__device__ float g_U[(size_t)T_PAD * BATCH * NH];

__device__ __forceinline__ float ex2a(float x) {
    float r; asm("ex2.approx.f32 %0, %1;" : "=f"(r) : "f"(x)); return r;
}
__device__ __forceinline__ float rcpa(float x) {
    float r; asm("rcp.approx.f32 %0, %1;" : "=f"(r) : "f"(x)); return r;
}
__device__ __forceinline__ u64 pack2(float lo, float hi) {
    u64 r; asm("mov.b64 %0, {%1, %2};" : "=l"(r) : "f"(lo), "f"(hi)); return r;
}
__device__ __forceinline__ void unpack2(u64 v, float& lo, float& hi) {
    asm("mov.b64 {%0, %1}, %2;" : "=f"(lo), "=f"(hi) : "l"(v));
}
__device__ __forceinline__ u64 fma2(u64 a, u64 b, u64 c) {
    u64 d; asm("fma.rn.f32x2 %0, %1, %2, %3;" : "=l"(d) : "l"(a), "l"(b), "l"(c)); return d;
}
__device__ __forceinline__ u64 add2(u64 a, u64 b) {
    u64 d; asm("add.rn.f32x2 %0, %1, %2;" : "=l"(d) : "l"(a), "l"(b)); return d;
}

// ============================================================================
// Pass 1: U[t][b][j] = S*b_j + S*sum_k Wh[k][j] + sum_k xe[t,b,k] * (S*Wx[k][j])
// Throughput pass, memory bound. One warp per (t,b) row at a time.
// ============================================================================
__global__ void __launch_bounds__(256) rnn_pass1(
    const int*   __restrict__ x,      // (T, B)
    const float* __restrict__ emb,    // (32000, 32)
    const float* __restrict__ W_rnn,  // (64, 32)
    const float* __restrict__ b_rnn)  // (32,)
{
    const int j     = threadIdx.x & 31;
    const int wglob = blockIdx.x * (blockDim.x >> 5) + (threadIdx.x >> 5);
    const int nwarp = gridDim.x * (blockDim.x >> 5);
    const float S = 2.885390081777926814f;  // 2*log2(e)

    u64 wx2p[16];
    #pragma unroll
    for (int m = 0; m < 16; m++) {
        float wx0 = W_rnn[(2*m+0)*NH + j];
        float wx1 = W_rnn[(2*m+1)*NH + j];
        wx2p[m] = pack2(S*wx0, S*wx1);
    }
    float whsum = 0.f;
    #pragma unroll
    for (int k = 0; k < NH; k++) whsum += S * W_rnn[(NH + k)*NH + j];
    const u64 basep = pack2(S * b_rnn[j] + whsum, 0.f);
    const u64 zerop = pack2(0.f, 0.f);
    const ulonglong2* emb16 = reinterpret_cast<const ulonglong2*>(emb);

    const int total = T_STEPS * BATCH;
    for (int row = wglob; row < total; row += nwarp) {
        int idx = __ldg(x + row);
        const ulonglong2* pe = emb16 + (long long)idx * 8;
        ulonglong2 v0 = __ldg(pe+0), v1 = __ldg(pe+1), v2 = __ldg(pe+2), v3 = __ldg(pe+3);
        ulonglong2 v4 = __ldg(pe+4), v5 = __ldg(pe+5), v6 = __ldg(pe+6), v7 = __ldg(pe+7);
        u64 a0 = basep, a1 = zerop, a2 = zerop, a3 = zerop;
        a0 = fma2(v0.x, wx2p[0],  a0);  a1 = fma2(v0.y, wx2p[1],  a1);
        a2 = fma2(v1.x, wx2p[2],  a2);  a3 = fma2(v1.y, wx2p[3],  a3);
        a0 = fma2(v2.x, wx2p[4],  a0);  a1 = fma2(v2.y, wx2p[5],  a1);
        a2 = fma2(v3.x, wx2p[6],  a2);  a3 = fma2(v3.y, wx2p[7],  a3);
        a0 = fma2(v4.x, wx2p[8],  a0);  a1 = fma2(v4.y, wx2p[9],  a1);
        a2 = fma2(v5.x, wx2p[10], a2);  a3 = fma2(v5.y, wx2p[11], a3);
        a0 = fma2(v6.x, wx2p[12], a0);  a1 = fma2(v6.y, wx2p[13], a1);
        a2 = fma2(v7.x, wx2p[14], a2);  a3 = fma2(v7.y, wx2p[15], a3);
        a0 = add2(a0, a1);  a2 = add2(a2, a3);  a0 = add2(a0, a2);
        float lo, hi; unpack2(a0, lo, hi);
        g_U[(size_t)row * NH + j] = lo + hi;
    }
}

// ============================================================================
// Pass 2: the recurrence. One warp per batch row; lane j = hidden unit j.
// Broadcast r = 1/(1+2^z); h = 1-2r folded into pre-scaled weights.
//   z_j = u_j + sum_k r_k * (-2S*Wh[k][j])
// ============================================================================

// One step. RD/WR: double-buffered smem r-vector. P: prefetch pipe slot.
#define STEP2(RD, WR, P)                                                        \
  {                                                                             \
    __syncwarp();                                                               \
    const ulonglong2* rb = reinterpret_cast<const ulonglong2*>(RD);             \
    ulonglong2 v0 = rb[0], v1 = rb[1], v2 = rb[2], v3 = rb[3];                  \
    ulonglong2 v4 = rb[4], v5 = rb[5], v6 = rb[6], v7 = rb[7];                  \
    u64 a0 = pack2(up[P], 0.f), a1 = zerop, a2 = zerop, a3 = zerop;             \
    a0 = fma2(v0.x, nwhp[0],  a0);  a1 = fma2(v0.y, nwhp[1],  a1);              \
    a2 = fma2(v1.x, nwhp[2],  a2);  a3 = fma2(v1.y, nwhp[3],  a3);              \
    a0 = fma2(v2.x, nwhp[4],  a0);  a1 = fma2(v2.y, nwhp[5],  a1);              \
    a2 = fma2(v3.x, nwhp[6],  a2);  a3 = fma2(v3.y, nwhp[7],  a3);              \
    a0 = fma2(v4.x, nwhp[8],  a0);  a1 = fma2(v4.y, nwhp[9],  a1);              \
    a2 = fma2(v5.x, nwhp[10], a2);  a3 = fma2(v5.y, nwhp[11], a3);              \
    a0 = fma2(v6.x, nwhp[12], a0);  a1 = fma2(v6.y, nwhp[13], a1);              \
    a2 = fma2(v7.x, nwhp[14], a2);  a3 = fma2(v7.y, nwhp[15], a3);              \
    a0 = add2(a0, a1);  a2 = add2(a2, a3);  a0 = add2(a0, a2);                  \
    float zl, zh; unpack2(a0, zl, zh);                                          \
    float z = zl + zh;                                                          \
    float e = ex2a(z);                                                          \
    float r = rcpa(e + 1.0f);                                                   \
    (WR)[j] = r;                                                                \
    rlast = r;                                                                  \
    up[P] = __ldg(up_t + (P) * ROW_F);  /* refill slot P with u(t+P+8) */       \
  }

__global__ void __launch_bounds__(128, 1) rnn_pass2(
    const float* __restrict__ W_rnn,  // (64, 32)
    const float* __restrict__ W_cls,  // (32, 5)
    const float* __restrict__ b_cls,  // (5,)
    float*       __restrict__ out)    // (B, 5)
{
    __shared__ __align__(16) float rbuf[4][2][NH];

    const int warp = threadIdx.x >> 5;
    const int j    = threadIdx.x & 31;
    const int brow = (blockIdx.x << 2) + warp;
    const float S  = 2.885390081777926814f;

    u64 nwhp[16];
    #pragma unroll
    for (int m = 0; m < 16; m++) {
        float wh0 = W_rnn[(NH + 2*m+0)*NH + j];
        float wh1 = W_rnn[(NH + 2*m+1)*NH + j];
        nwhp[m] = pack2(-2.f*S*wh0, -2.f*S*wh1);
    }
    const u64 zerop = pack2(0.f, 0.f);

    const float* ubase = g_U + (size_t)brow * NH + j;

    // prime 8-deep prefetch pipe: up[p] = u(p)
    float up[8];
    #pragma unroll
    for (int p = 0; p < 8; p++) up[p] = __ldg(ubase + (size_t)p * ROW_F);

    float* buf0 = &rbuf[warp][0][0];
    float* buf1 = &rbuf[warp][1][0];
    buf0[j] = 0.5f;     // h_{-1}=0 -> r = (1-h)/2 = 0.5
    float rlast = 0.5f;

    // main loop: 8 steps / iter, fixed buffer parity; prefetch distance 8
    const float* up_t = ubase + (size_t)8 * ROW_F;
    for (int t = 0; t < T_STEPS; t += 8) {
        STEP2(buf0, buf1, 0);
        STEP2(buf1, buf0, 1);
        STEP2(buf0, buf1, 2);
        STEP2(buf1, buf0, 3);
        STEP2(buf0, buf1, 4);
        STEP2(buf1, buf0, 5);
        STEP2(buf0, buf1, 6);
        STEP2(buf1, buf0, 7);
        up_t += 8 * ROW_F;
    }

    // epilogue: y = h_final @ W_cls + b_cls, h = 1 - 2r
    float h = fmaf(-2.f, rlast, 1.f);
    #pragma unroll
    for (int c = 0; c < NC; c++) {
        float v = h * __ldg(W_cls + j * NC + c);
        #pragma unroll
        for (int off = 16; off; off >>= 1)
            v += __shfl_xor_sync(0xffffffffu, v, off);
        if (j == 0) out[brow * NC + c] = v + __ldg(b_cls + c);
    }
}

extern "C" void kernel_launch(void* const* d_in, const int* in_sizes, int n_in,
                              void* d_out, int out_size) {
    (void)in_sizes; (void)n_in; (void)out_size;
    rnn_pass1<<<1024, 256>>>(
        (const int*)d_in[0],
        (const float*)d_in[1],
        (const float*)d_in[2],
        (const float*)d_in[3]);
    rnn_pass2<<<BATCH / 4, 128>>>(
        (const float*)d_in[2],
        (const float*)d_in[4],
        (const float*)d_in[5],
        (float*)d_out);
}

// round 3
// speedup vs baseline: 1.7401x; 1.7401x over previous
#include <cuda_runtime.h>

#define T_STEPS 2048
#define BATCH   512
#define NH      32
#define NC      5

typedef unsigned long long u64;

__device__ __forceinline__ float tanha(float x) {
    float r; asm("tanh.approx.f32 %0, %1;" : "=f"(r) : "f"(x)); return r;
}
__device__ __forceinline__ u64 pack2(float lo, float hi) {
    u64 r; asm("mov.b64 %0, {%1, %2};" : "=l"(r) : "f"(lo), "f"(hi)); return r;
}
__device__ __forceinline__ void unpack2(u64 v, float& lo, float& hi) {
    asm("mov.b64 {%0, %1}, %2;" : "=f"(lo), "=f"(hi) : "l"(v));
}
__device__ __forceinline__ u64 fma2(u64 a, u64 b, u64 c) {
    u64 d; asm("fma.rn.f32x2 %0, %1, %2, %3;" : "=l"(d) : "l"(a), "l"(b), "l"(c)); return d;
}
__device__ __forceinline__ u64 add2(u64 a, u64 b) {
    u64 d; asm("add.rn.f32x2 %0, %1, %2;" : "=l"(d) : "l"(a), "l"(b)); return d;
}

// One step of h = tanh(u + h @ Wh), warp-synchronous smem broadcast, NO syncwarp:
// same-warp STS -> LDS is program-ordered through the LSU; asm volatile +
// memory clobbers pin the compiler ordering.
//  XES:   register stage holding xe row for step t+1 (consumed -> u(t+1)),
//         then refilled with xe row for step t+3 (address i3 = idx(t+3)).
//  TNEXT: clamped time index prefetched into the idx pipe (becomes i3 in 3 steps).
#define STEP(XES, TNEXT)                                                        \
  {                                                                             \
    asm volatile("st.shared.f32 [%0], %1;" :: "r"(sj), "f"(h) : "memory");      \
    u64 v0,v1,v2,v3,v4,v5,v6,v7,v8,v9,v10,v11,v12,v13,v14,v15;                  \
    asm volatile("ld.shared.v2.b64 {%0,%1},[%2];"   : "=l"(v0), "=l"(v1)  : "r"(sa)      : "memory"); \
    asm volatile("ld.shared.v2.b64 {%0,%1},[%2];"   : "=l"(v2), "=l"(v3)  : "r"(sa+16u)  : "memory"); \
    asm volatile("ld.shared.v2.b64 {%0,%1},[%2];"   : "=l"(v4), "=l"(v5)  : "r"(sa+32u)  : "memory"); \
    asm volatile("ld.shared.v2.b64 {%0,%1},[%2];"   : "=l"(v6), "=l"(v7)  : "r"(sa+48u)  : "memory"); \
    asm volatile("ld.shared.v2.b64 {%0,%1},[%2];"   : "=l"(v8), "=l"(v9)  : "r"(sa+64u)  : "memory"); \
    asm volatile("ld.shared.v2.b64 {%0,%1},[%2];"   : "=l"(v10),"=l"(v11) : "r"(sa+80u)  : "memory"); \
    asm volatile("ld.shared.v2.b64 {%0,%1},[%2];"   : "=l"(v12),"=l"(v13) : "r"(sa+96u)  : "memory"); \
    asm volatile("ld.shared.v2.b64 {%0,%1},[%2];"   : "=l"(v14),"=l"(v15) : "r"(sa+112u) : "memory"); \
    u64 a0 = pack2(ucur, 0.f), a1 = zerop, a2 = zerop, a3 = zerop;              \
    a0 = fma2(v0,  whp[0],  a0);  a1 = fma2(v1,  whp[1],  a1);                  \
    a2 = fma2(v2,  whp[2],  a2);  a3 = fma2(v3,  whp[3],  a3);                  \
    a0 = fma2(v4,  whp[4],  a0);  a1 = fma2(v5,  whp[5],  a1);                  \
    a2 = fma2(v6,  whp[6],  a2);  a3 = fma2(v7,  whp[7],  a3);                  \
    a0 = fma2(v8,  whp[8],  a0);  a1 = fma2(v9,  whp[9],  a1);                  \
    a2 = fma2(v10, whp[10], a2);  a3 = fma2(v11, whp[11], a3);                  \
    a0 = fma2(v12, whp[12], a0);  a1 = fma2(v13, whp[13], a1);                  \
    a2 = fma2(v14, whp[14], a2);  a3 = fma2(v15, whp[15], a3);                  \
    a0 = add2(a0, a1);  a2 = add2(a2, a3);  a0 = add2(a0, a2);                  \
    float zl, zh; unpack2(a0, zl, zh);                                          \
    h = tanha(zl + zh);                                                         \
    /* off critical path: u for step t+1 from staged xe */                      \
    u64 n0 = basep, n1 = zerop, n2 = zerop, n3 = zerop;                         \
    n0 = fma2(XES[0].x, wxp[0],  n0);  n1 = fma2(XES[0].y, wxp[1],  n1);        \
    n2 = fma2(XES[1].x, wxp[2],  n2);  n3 = fma2(XES[1].y, wxp[3],  n3);        \
    n0 = fma2(XES[2].x, wxp[4],  n0);  n1 = fma2(XES[2].y, wxp[5],  n1);        \
    n2 = fma2(XES[3].x, wxp[6],  n2);  n3 = fma2(XES[3].y, wxp[7],  n3);        \
    n0 = fma2(XES[4].x, wxp[8],  n0);  n1 = fma2(XES[4].y, wxp[9],  n1);        \
    n2 = fma2(XES[5].x, wxp[10], n2);  n3 = fma2(XES[5].y, wxp[11], n3);        \
    n0 = fma2(XES[6].x, wxp[12], n0);  n1 = fma2(XES[6].y, wxp[13], n1);        \
    n2 = fma2(XES[7].x, wxp[14], n2);  n3 = fma2(XES[7].y, wxp[15], n3);        \
    n0 = add2(n0, n1);  n2 = add2(n2, n3);  n0 = add2(n0, n2);                  \
    float ul, uh; unpack2(n0, ul, uh);                                          \
    ucur = ul + uh;                                                             \
    /* prefetch embedding row for step t+3 (i3 loaded 3 steps ago) */           \
    {                                                                           \
        const ulonglong2* pe = emb16 + (long long)i3 * 8;                       \
        _Pragma("unroll")                                                       \
        for (int m = 0; m < 8; m++) XES[m] = __ldg(pe + m);                     \
    }                                                                           \
    i3 = i4; i4 = i5;                                                           \
    i5 = __ldg(xb + (TNEXT) * BATCH);                                           \
  }

__global__ void __launch_bounds__(128, 1) rnn_fused(
    const int*   __restrict__ x,      // (T, B) int32
    const float* __restrict__ emb,    // (32000, 32)
    const float* __restrict__ W_rnn,  // (64, 32): rows 0..31 = Wx, rows 32..63 = Wh
    const float* __restrict__ b_rnn,  // (32,)
    const float* __restrict__ W_cls,  // (32, 5)
    const float* __restrict__ b_cls,  // (5,)
    float*       __restrict__ out)    // (B, 5)
{
    __shared__ __align__(16) float sb[4][NH];

    const int warp = threadIdx.x >> 5;
    const int j    = threadIdx.x & 31;
    const int brow = (blockIdx.x << 2) + warp;

    // smem addresses (generic -> shared u32)
    unsigned sa;
    {
        unsigned long long gp = (unsigned long long)&sb[warp][0];
        asm("{ .reg .u64 t; cvta.to.shared.u64 t, %1; cvt.u32.u64 %0, t; }"
            : "=r"(sa) : "l"(gp));
    }
    const unsigned sj = sa + 4u * (unsigned)j;

    // Per-lane weight columns packed in k-pairs for fma.rn.f32x2 (plain h-domain).
    u64 wxp[NH/2];
    u64 whp[NH/2];
    #pragma unroll
    for (int m = 0; m < NH/2; m++) {
        wxp[m] = pack2(W_rnn[(2*m+0)*NH + j],      W_rnn[(2*m+1)*NH + j]);
        whp[m] = pack2(W_rnn[(NH + 2*m+0)*NH + j], W_rnn[(NH + 2*m+1)*NH + j]);
    }
    const u64 basep = pack2(b_rnn[j], 0.f);
    const u64 zerop = pack2(0.f, 0.f);

    const int* xb = x + brow;
    const ulonglong2* emb16 = reinterpret_cast<const ulonglong2*>(emb);

    // ---- prologue: prime idx + embedding pipelines ----
    int id0 = __ldg(xb + 0 * BATCH);
    int id1 = __ldg(xb + 1 * BATCH);
    int id2 = __ldg(xb + 2 * BATCH);
    int i3  = __ldg(xb + 3 * BATCH);
    int i4  = __ldg(xb + 4 * BATCH);
    int i5  = __ldg(xb + 5 * BATCH);

    float ucur;
    {
        const ulonglong2* p0 = emb16 + (long long)id0 * 8;
        u64 a = basep, b = zerop;
        #pragma unroll
        for (int m = 0; m < 8; m++) {
            ulonglong2 v = __ldg(p0 + m);
            a = fma2(v.x, wxp[2*m+0], a);
            b = fma2(v.y, wxp[2*m+1], b);
        }
        a = add2(a, b);
        float lo, hi; unpack2(a, lo, hi);
        ucur = lo + hi;   // u for step 0
    }

    ulonglong2 xeA[8], xeB[8];
    {
        const ulonglong2* p1 = emb16 + (long long)id1 * 8;
        const ulonglong2* p2 = emb16 + (long long)id2 * 8;
        #pragma unroll
        for (int m = 0; m < 8; m++) xeA[m] = __ldg(p1 + m);  // xe(1)
        #pragma unroll
        for (int m = 0; m < 8; m++) xeB[m] = __ldg(p2 + m);  // xe(2)
    }

    float h = 0.f;   // h_{-1} = 0; step 0's STS writes the zeros it then reads

    // ---- main recurrence: 2 steps per iteration ----
    for (int t = 0; t < T_STEPS; t += 2) {
        int t6 = (t + 6 < T_STEPS) ? (t + 6) : (T_STEPS - 1);
        STEP(xeA, t6);
        int t7 = (t + 7 < T_STEPS) ? (t + 7) : (T_STEPS - 1);
        STEP(xeB, t7);
    }

    // ---- epilogue: y = h_final @ W_cls + b_cls ----
    #pragma unroll
    for (int c = 0; c < NC; c++) {
        float v = h * __ldg(W_cls + j * NC + c);
        #pragma unroll
        for (int off = 16; off; off >>= 1)
            v += __shfl_xor_sync(0xffffffffu, v, off);
        if (j == 0) out[brow * NC + c] = v + __ldg(b_cls + c);
    }
}

extern "C" void kernel_launch(void* const* d_in, const int* in_sizes, int n_in,
                              void* d_out, int out_size) {
    (void)in_sizes; (void)n_in; (void)out_size;
    rnn_fused<<<BATCH / 4, 128>>>(
        (const int*)d_in[0],
        (const float*)d_in[1],
        (const float*)d_in[2],
        (const float*)d_in[3],
        (const float*)d_in[4],
        (const float*)d_in[5],
        (float*)d_out);
}

// round 4
// speedup vs baseline: 1.8712x; 1.0753x over previous
#include <cuda_runtime.h>

#define T_STEPS 2048
#define BATCH   512
#define NH      32
#define NC      5
#define NWORD   32000

typedef unsigned long long u64;

// Precomputed input-projection table: E2[w][j] = b_rnn[j] + sum_k emb[w][k]*Wx[k][j]
__device__ float g_E2[NWORD * NH];

__device__ __forceinline__ float tanha(float x) {
    float r; asm("tanh.approx.f32 %0, %1;" : "=f"(r) : "f"(x)); return r;
}
__device__ __forceinline__ u64 pack2(float lo, float hi) {
    u64 r; asm("mov.b64 %0, {%1, %2};" : "=l"(r) : "f"(lo), "f"(hi)); return r;
}
__device__ __forceinline__ void unpack2(u64 v, float& lo, float& hi) {
    asm("mov.b64 {%0, %1}, %2;" : "=f"(lo), "=f"(hi) : "l"(v));
}
__device__ __forceinline__ u64 fma2(u64 a, u64 b, u64 c) {
    u64 d; asm("fma.rn.f32x2 %0, %1, %2, %3;" : "=l"(d) : "l"(a), "l"(b), "l"(c)); return d;
}
__device__ __forceinline__ u64 add2(u64 a, u64 b) {
    u64 d; asm("add.rn.f32x2 %0, %1, %2;" : "=l"(d) : "l"(a), "l"(b)); return d;
}

// ============================================================================
// Kernel 1: build E2 table. One warp per word. Memory-bound, ~8 MB traffic.
// ============================================================================
__global__ void __launch_bounds__(256) build_e2(
    const float* __restrict__ emb,    // (32000, 32)
    const float* __restrict__ W_rnn,  // (64, 32): rows 0..31 = Wx
    const float* __restrict__ b_rnn)  // (32,)
{
    const int j = threadIdx.x & 31;
    const int w = blockIdx.x * (blockDim.x >> 5) + (threadIdx.x >> 5);

    u64 wxp[16];
    #pragma unroll
    for (int m = 0; m < 16; m++)
        wxp[m] = pack2(W_rnn[(2*m+0)*NH + j], W_rnn[(2*m+1)*NH + j]);
    const u64 basep = pack2(b_rnn[j], 0.f);
    const u64 zerop = pack2(0.f, 0.f);

    if (w >= NWORD) return;
    const ulonglong2* pe = reinterpret_cast<const ulonglong2*>(emb) + (long long)w * 8;
    ulonglong2 v0 = __ldg(pe+0), v1 = __ldg(pe+1), v2 = __ldg(pe+2), v3 = __ldg(pe+3);
    ulonglong2 v4 = __ldg(pe+4), v5 = __ldg(pe+5), v6 = __ldg(pe+6), v7 = __ldg(pe+7);
    u64 a0 = basep, a1 = zerop, a2 = zerop, a3 = zerop;
    a0 = fma2(v0.x, wxp[0],  a0);  a1 = fma2(v0.y, wxp[1],  a1);
    a2 = fma2(v1.x, wxp[2],  a2);  a3 = fma2(v1.y, wxp[3],  a3);
    a0 = fma2(v2.x, wxp[4],  a0);  a1 = fma2(v2.y, wxp[5],  a1);
    a2 = fma2(v3.x, wxp[6],  a2);  a3 = fma2(v3.y, wxp[7],  a3);
    a0 = fma2(v4.x, wxp[8],  a0);  a1 = fma2(v4.y, wxp[9],  a1);
    a2 = fma2(v5.x, wxp[10], a2);  a3 = fma2(v5.y, wxp[11], a3);
    a0 = fma2(v6.x, wxp[12], a0);  a1 = fma2(v6.y, wxp[13], a1);
    a2 = fma2(v7.x, wxp[14], a2);  a3 = fma2(v7.y, wxp[15], a3);
    a0 = add2(a0, a1);  a2 = add2(a2, a3);  a0 = add2(a0, a2);
    float lo, hi; unpack2(a0, lo, hi);
    g_E2[w * NH + j] = lo + hi;
}

// ============================================================================
// Kernel 2: recurrence. One warp per batch row, lane j = hidden unit j.
// h broadcast via register shuffles (no smem round trip on the chain).
// u(t) = E2[x[t]][j]  — single coalesced gather, 8-step register pipeline.
// ============================================================================
__global__ void __launch_bounds__(128, 1) rnn_rec(
    const int*   __restrict__ x,      // (T, B)
    const float* __restrict__ W_rnn,  // (64, 32): rows 32..63 = Wh
    const float* __restrict__ W_cls,  // (32, 5)
    const float* __restrict__ b_cls,  // (5,)
    float*       __restrict__ out)    // (B, 5)
{
    const int warp = threadIdx.x >> 5;
    const int j    = threadIdx.x & 31;
    const int brow = (blockIdx.x << 2) + warp;

    u64 whp[16];
    #pragma unroll
    for (int m = 0; m < 16; m++)
        whp[m] = pack2(W_rnn[(NH + 2*m+0)*NH + j], W_rnn[(NH + 2*m+1)*NH + j]);
    const u64 zerop = pack2(0.f, 0.f);

    const int*   xb  = x + brow;
    const float* e2j = g_E2 + j;

    // ---- prime 8-deep idx + u pipelines ----
    int   ip[8];
    float up[8];
    #pragma unroll
    for (int p = 0; p < 8; p++) ip[p] = __ldg(xb + p * BATCH);            // idx(0..7)
    #pragma unroll
    for (int p = 0; p < 8; p++) up[p] = __ldg(e2j + (size_t)ip[p] * NH);  // u(0..7)
    #pragma unroll
    for (int p = 0; p < 8; p++) ip[p] = __ldg(xb + (p + 8) * BATCH);      // idx(8..15)

    float h = 0.f;

    for (int t = 0; t < T_STEPS; t += 8) {
        #pragma unroll
        for (int p = 0; p < 8; p++) {
            // broadcast h_k to all lanes: 32 independent shuffles off one tanh result
            u64 v[16];
            #pragma unroll
            for (int m = 0; m < 16; m++) {
                float lo = __shfl_sync(0xffffffffu, h, 2*m);
                float hi = __shfl_sync(0xffffffffu, h, 2*m + 1);
                v[m] = pack2(lo, hi);
            }
            u64 a0 = pack2(up[p], 0.f), a1 = zerop, a2 = zerop, a3 = zerop;
            a0 = fma2(v[0],  whp[0],  a0);  a1 = fma2(v[1],  whp[1],  a1);
            a2 = fma2(v[2],  whp[2],  a2);  a3 = fma2(v[3],  whp[3],  a3);
            a0 = fma2(v[4],  whp[4],  a0);  a1 = fma2(v[5],  whp[5],  a1);
            a2 = fma2(v[6],  whp[6],  a2);  a3 = fma2(v[7],  whp[7],  a3);
            a0 = fma2(v[8],  whp[8],  a0);  a1 = fma2(v[9],  whp[9],  a1);
            a2 = fma2(v[10], whp[10], a2);  a3 = fma2(v[11], whp[11], a3);
            a0 = fma2(v[12], whp[12], a0);  a1 = fma2(v[13], whp[13], a1);
            a2 = fma2(v[14], whp[14], a2);  a3 = fma2(v[15], whp[15], a3);
            a0 = add2(a0, a1);  a2 = add2(a2, a3);  a0 = add2(a0, a2);
            float zl, zh; unpack2(a0, zl, zh);
            h = tanha(zl + zh);

            // refills (off critical path, 8-step slack each)
            up[p] = __ldg(e2j + (size_t)ip[p] * NH);        // u(t+p+8)
            int tn = t + p + 16;
            tn = (tn < T_STEPS) ? tn : (T_STEPS - 1);
            ip[p] = __ldg(xb + tn * BATCH);                 // idx(t+p+16)
        }
    }

    // ---- epilogue: y = h_final @ W_cls + b_cls ----
    #pragma unroll
    for (int c = 0; c < NC; c++) {
        float vv = h * __ldg(W_cls + j * NC + c);
        #pragma unroll
        for (int off = 16; off; off >>= 1)
            vv += __shfl_xor_sync(0xffffffffu, vv, off);
        if (j == 0) out[brow * NC + c] = vv + __ldg(b_cls + c);
    }
}

extern "C" void kernel_launch(void* const* d_in, const int* in_sizes, int n_in,
                              void* d_out, int out_size) {
    (void)in_sizes; (void)n_in; (void)out_size;
    build_e2<<<(NWORD + 7) / 8, 256>>>(
        (const float*)d_in[1],
        (const float*)d_in[2],
        (const float*)d_in[3]);
    rnn_rec<<<BATCH / 4, 128>>>(
        (const int*)d_in[0],
        (const float*)d_in[2],
        (const float*)d_in[4],
        (const float*)d_in[5],
        (float*)d_out);
}